// round 15
// baseline (speedup 1.0000x reference)
#include <cuda_runtime.h>
#include <cuda_fp16.h>
#include <cstdint>

#define BB 8
#define SS 2048
#define DD 512
#define SCALEV 0.04419417382415922f   // 1/sqrt(512)

#define BM 128
#define BN 128
#define BK 32

// ---- single-term fp16 GEMM: 2 tiles, 4 stages, prefetch 3, SW64 ----
#define PV_TBYTES 8192
#define PV_STAGE (2*PV_TBYTES)          // 16384
#define PV_NSTAGE 4
#define PV_SMEM (PV_NSTAGE*PV_STAGE)    // 65536

// ---- scratch (device globals zero-init; never-written rows stay 0) ----
__device__ __half g_xf[BB*SS*DD];
__device__ __half g_wf[3*DD*DD];
__device__ __half g_qf[BB*SS*DD], g_kf[BB*SS*DD];
__device__ float g_v[BB*SS*DD];
__device__ __half g_vtf[BB*DD*SS];
__device__ float g_vmean[BB*DD];
__device__ float g_p[(size_t)BB*SS*SS];
__device__ __half g_pf[(size_t)BB*SS*SS];

// ---- side stream + events (host objects; static init, reused every call) ----
struct StreamPack {
    cudaStream_t s1;
    cudaEvent_t e_fork, e_join;
    StreamPack() {
        cudaStreamCreateWithFlags(&s1, cudaStreamNonBlocking);
        cudaEventCreateWithFlags(&e_fork, cudaEventDisableTiming);
        cudaEventCreateWithFlags(&e_join, cudaEventDisableTiming);
    }
};
static StreamPack g_sp;

// ============================ helpers ============================
__device__ __forceinline__ uint32_t smem_u32(const void* p) {
    uint32_t a;
    asm("{ .reg .u64 t; cvta.to.shared.u64 t, %1; cvt.u32.u64 %0, t; }" : "=r"(a) : "l"(p));
    return a;
}
__device__ __forceinline__ void cp16(uint32_t dst, const void* src) {
    asm volatile("cp.async.cg.shared.global [%0], [%1], 16;" :: "r"(dst), "l"(src));
}
#define CP_COMMIT() asm volatile("cp.async.commit_group;" ::: "memory")
#define CP_WAIT2()  asm volatile("cp.async.wait_group 2;" ::: "memory")
#define CP_WAIT0()  asm volatile("cp.async.wait_group 0;" ::: "memory")

__device__ __forceinline__ void mma_f16(float* c, const uint32_t* a, uint32_t b0, uint32_t b1) {
    asm volatile(
        "mma.sync.aligned.m16n8k16.row.col.f32.f16.f16.f32 "
        "{%0,%1,%2,%3},{%4,%5,%6,%7},{%8,%9},{%0,%1,%2,%3};"
        : "+f"(c[0]), "+f"(c[1]), "+f"(c[2]), "+f"(c[3])
        : "r"(a[0]), "r"(a[1]), "r"(a[2]), "r"(a[3]), "r"(b0), "r"(b1));
}

__device__ __forceinline__ void ldm_x4(uint32_t* r, uint32_t addr) {
    asm volatile("ldmatrix.sync.aligned.m8n8.x4.shared.b16 {%0,%1,%2,%3}, [%4];"
        : "=r"(r[0]), "=r"(r[1]), "=r"(r[2]), "=r"(r[3]) : "r"(addr));
}

// ============================ single-term fp16 mainloop ============================
__device__ __forceinline__ void pv_load_chunk(
    const __half* __restrict__ P, size_t ldp,
    const __half* __restrict__ Vt, size_t ldv,
    int c, int s, uint32_t smaddr, int tid)
{
    uint32_t base = smaddr + s * PV_STAGE;
    const __half* p = P + (size_t)c * BK;
    const __half* v = Vt + (size_t)c * BK;
#pragma unroll
    for (int i = 0; i < 2; i++) {
        int idx = tid + i * 256;
        int r = idx >> 2, cb = (idx & 3) * 16;
        uint32_t doff = (uint32_t)r * 64 + (cb ^ ((r & 6) << 3));
        cp16(base + doff,             p + (size_t)r * ldp + (cb >> 1));
        cp16(base + PV_TBYTES + doff, v + (size_t)r * ldv + (cb >> 1));
    }
}

__device__ __forceinline__ void pv_mainloop(
    const __half* __restrict__ P, size_t ldp,
    const __half* __restrict__ Vt, size_t ldv,
    int nchunks, uint32_t smaddr,
    float acc[2][8][4])
{
    const int tid = threadIdx.x;
    const int lane = tid & 31, wid = tid >> 5;
    const int q = lane >> 3, r = lane & 7;
    const int m_base = (wid & 3) * 32;
    const int n_base = (wid >> 2) * 64;

    const int arow = m_base + (q & 1) * 8 + r;
    const int brow = n_base + (q >> 1) * 8 + r;
    const uint32_t aoff0 = (uint32_t)arow * 64 + ((arow & 6) << 3);
    const uint32_t boff0 = (uint32_t)brow * 64 + ((brow & 6) << 3);
    const uint32_t acol = (uint32_t)(q >> 1) * 16;
    const uint32_t bcol = (uint32_t)(q & 1) * 16;

#pragma unroll
    for (int i = 0; i < 3; i++) {
        if (i < nchunks) pv_load_chunk(P, ldp, Vt, ldv, i, i, smaddr, tid);
        CP_COMMIT();
    }

    int s = 0;
    for (int c = 0; c < nchunks; c++) {
        CP_WAIT2();
        __syncthreads();
        int s3 = s + 3 >= PV_NSTAGE ? s + 3 - PV_NSTAGE : s + 3;
        if (c + 3 < nchunks)
            pv_load_chunk(P, ldp, Vt, ldv, c + 3, s3, smaddr, tid);
        CP_COMMIT();

        uint32_t sbase = smaddr + s * PV_STAGE;
#pragma unroll
        for (int ks = 0; ks < 2; ks++) {
            uint32_t axo = aoff0 ^ (acol + ks * 32);
            uint32_t bxo = boff0 ^ (bcol + ks * 32);
            uint32_t ah[2][4];
            ldm_x4(ah[0], sbase + axo);
            ldm_x4(ah[1], sbase + 1024 + axo);
#pragma unroll
            for (int p = 0; p < 4; p++) {
                uint32_t bh[4];
                ldm_x4(bh, sbase + PV_TBYTES + p*1024 + bxo);
                mma_f16(acc[0][2*p],   ah[0], bh[0], bh[1]);
                mma_f16(acc[1][2*p],   ah[1], bh[0], bh[1]);
                mma_f16(acc[0][2*p+1], ah[0], bh[2], bh[3]);
                mma_f16(acc[1][2*p+1], ah[1], bh[2], bh[3]);
            }
        }
        s = (s + 1 == PV_NSTAGE) ? 0 : s + 1;
    }
    CP_WAIT0();
}

// ============================ split inputs: all -> single fp16 ============================
#define NX4 (BB*SS*DD/4)
#define NW4 (DD*DD/4)
__global__ __launch_bounds__(256) void split_k(
    const float4* __restrict__ x, const float4* __restrict__ Wq,
    const float4* __restrict__ Wk, const float4* __restrict__ Wv)
{
    int i = blockIdx.x * 256 + threadIdx.x;
    const float4* in; __half2* o2; int j;
    if (i < NX4) {
        in = x; j = i; o2 = (__half2*)g_xf;
    } else {
        int t = i - NX4;
        int w = t / NW4; j = t - w * NW4;
        in = (w == 0) ? Wq : (w == 1) ? Wk : Wv;
        o2 = (__half2*)(g_wf + (size_t)w * DD * DD);
    }
    float4 v = in[j];
    o2[j*2]   = __halves2half2(__float2half_rn(v.x), __float2half_rn(v.y));
    o2[j*2+1] = __halves2half2(__float2half_rn(v.z), __float2half_rn(v.w));
}

// ============================ kernel 1: QKV (zbase selects q/k vs v) ============================
__global__ __launch_bounds__(256, 2) void qkv_k(
    const int* __restrict__ ev, int zbase,
    const float* __restrict__ bq, const float* __restrict__ bk, const float* __restrict__ bv)
{
    int m0 = blockIdx.x * BM;
    int z = zbase + blockIdx.z;
    if (z < 2) {                        // q/k rows >= L never read downstream
        int b = m0 >> 11;
        if ((m0 & (SS - 1)) >= ev[b]) return;
    }

    extern __shared__ __align__(128) uint32_t dsm[];
    uint32_t smaddr = smem_u32(dsm);

    int e0 = blockIdx.y * BN;
    const float* bias = (z == 0) ? bq : (z == 1) ? bk : bv;

    float acc[2][8][4] = {};
    pv_mainloop(g_xf + (size_t)m0 * DD, DD,
                g_wf + (size_t)z * DD * DD + (size_t)e0 * DD, DD,
                DD / BK, smaddr, acc);

    int tid = threadIdx.x, lane = tid & 31, wid = tid >> 5;
    int gid = lane >> 2, tig = lane & 3;
    int row0 = m0 + (wid & 3) * 32 + gid;
    int col0 = e0 + (wid >> 2) * 64 + tig * 2;
#pragma unroll
    for (int mf = 0; mf < 2; mf++)
#pragma unroll
    for (int h = 0; h < 2; h++) {
        int row = row0 + mf * 16 + h * 8;
#pragma unroll
        for (int nf = 0; nf < 8; nf++) {
            int col = col0 + nf * 8;
            float y0 = acc[mf][nf][h*2+0] + bias[col];
            float y1 = acc[mf][nf][h*2+1] + bias[col+1];
            size_t off = (size_t)row * DD + col;
            if (z == 2) {
                *(float2*)(g_v + off) = make_float2(y0, y1);
            } else {
                __half* o = (z == 0) ? g_qf : g_kf;
                *(__half2*)(o + off) = __halves2half2(__float2half_rn(y0), __float2half_rn(y1));
            }
        }
    }
}

// ============================ kernel 2: scores ============================
__global__ __launch_bounds__(256, 2) void scores_k(const int* __restrict__ ev)
{
    int b = blockIdx.z;
    int L = ev[b];
    int q0 = blockIdx.x * BM;
    int k0 = blockIdx.y * BN;
    if (q0 >= L || k0 >= L) return;

    extern __shared__ __align__(128) uint32_t dsm[];
    uint32_t smaddr = smem_u32(dsm);

    float acc[2][8][4] = {};
    size_t qoff = ((size_t)b * SS + q0) * DD;
    size_t koff = ((size_t)b * SS + k0) * DD;
    pv_mainloop(g_qf + qoff, DD, g_kf + koff, DD, DD / BK, smaddr, acc);

    float* P = g_p + (size_t)b * SS * SS;
    int tid = threadIdx.x, lane = tid & 31, wid = tid >> 5;
    int gid = lane >> 2, tig = lane & 3;
    int row0 = q0 + (wid & 3) * 32 + gid;
    int col0 = k0 + (wid >> 2) * 64 + tig * 2;
#pragma unroll
    for (int mf = 0; mf < 2; mf++)
#pragma unroll
    for (int h = 0; h < 2; h++) {
        int q = row0 + mf * 16 + h * 8;
        if (q >= L) continue;
#pragma unroll
        for (int nf = 0; nf < 8; nf++) {
            int k = col0 + nf * 8;
            if (k + 1 < L) {
                float2 v;
                v.x = acc[mf][nf][h*2+0] * SCALEV;
                v.y = acc[mf][nf][h*2+1] * SCALEV;
                *(float2*)(P + (size_t)q * SS + k) = v;
            } else if (k < L) {
                P[(size_t)q * SS + k] = acc[mf][nf][h*2+0] * SCALEV;
            }
        }
    }
}

// ============================ kernel 3: softmax (warp-per-row, float4) ============================
__global__ __launch_bounds__(256) void softmax_k(const int* __restrict__ ev)
{
    int b = blockIdx.y;
    int L = ev[b];
    int wid = threadIdx.x >> 5, lane = threadIdx.x & 31;
    int q = blockIdx.x * 8 + wid;
    if (q >= L) return;                 // handled via vmean in pv

    size_t off = ((size_t)b * SS + q) * SS;
    const float4* row4 = (const float4*)(g_p + off);

    float4 v[16];
    float m = -3.4e38f;
#pragma unroll
    for (int i = 0; i < 16; i++) {
        int k = lane * 4 + i * 128;
        float4 t = row4[lane + i * 32];
        t.x = (k + 0 < L) ? t.x : -3.4e38f;
        t.y = (k + 1 < L) ? t.y : -3.4e38f;
        t.z = (k + 2 < L) ? t.z : -3.4e38f;
        t.w = (k + 3 < L) ? t.w : -3.4e38f;
        v[i] = t;
        m = fmaxf(m, fmaxf(fmaxf(t.x, t.y), fmaxf(t.z, t.w)));
    }
#pragma unroll
    for (int o = 16; o > 0; o >>= 1) m = fmaxf(m, __shfl_xor_sync(0xffffffffu, m, o));

    float s = 0.f;
#pragma unroll
    for (int i = 0; i < 16; i++) {
        v[i].x = __expf(v[i].x - m);    // exp(-huge) underflows to 0 for masked
        v[i].y = __expf(v[i].y - m);
        v[i].z = __expf(v[i].z - m);
        v[i].w = __expf(v[i].w - m);
        s += (v[i].x + v[i].y) + (v[i].z + v[i].w);
    }
#pragma unroll
    for (int o = 16; o > 0; o >>= 1) s += __shfl_xor_sync(0xffffffffu, s, o);
    float inv = 1.0f / s;

    int pad = (L + 31) & ~31;
    if (pad > SS) pad = SS;
    __half2* out2 = (__half2*)(g_pf + off);
#pragma unroll
    for (int i = 0; i < 16; i++) {
        int k = lane * 4 + i * 128;
        if (k < pad) {
            out2[(k >> 1)]     = __halves2half2(__float2half_rn(v[i].x * inv),
                                                __float2half_rn(v[i].y * inv));
            out2[(k >> 1) + 1] = __halves2half2(__float2half_rn(v[i].z * inv),
                                                __float2half_rn(v[i].w * inv));
        }
    }
}

// ============================ transpose V -> vT (fp16; dead columns skipped) ============================
__global__ void vtrans_k(const int* __restrict__ ev)
{
    __shared__ float t[32][33];
    int b = blockIdx.z;
    int s0 = blockIdx.x * 32;
    int pad = (ev[b] + 31) & ~31;
    if (s0 >= pad) return;
    int d0 = blockIdx.y * 32;
    int tx = threadIdx.x, ty = threadIdx.y;
    const float* v = g_v + (size_t)b * SS * DD;
#pragma unroll
    for (int i = 0; i < 4; i++)
        t[ty + i*8][tx] = v[(size_t)(s0 + ty + i*8) * DD + d0 + tx];
    __syncthreads();
#pragma unroll
    for (int i = 0; i < 4; i++) {
        size_t o = (size_t)b * DD * SS + (size_t)(d0 + ty + i*8) * SS + s0 + tx;
        g_vtf[o] = __float2half_rn(t[tx][ty + i*8]);
    }
}

// ============================ vmean (coalesced, deterministic) ============================
__global__ __launch_bounds__(256) void vmean_k()
{
    __shared__ float part[8][32];
    int b = blockIdx.x;
    int d0 = blockIdx.y * 32;
    int tid = threadIdx.x;
    int c = tid & 31, h = tid >> 5;

    const float* v = g_v + (size_t)b * SS * DD + d0 + c;
    float s = 0.f;
    for (int r = h; r < SS; r += 8)
        s += v[(size_t)r * DD];
    part[h][c] = s;
    __syncthreads();

    if (h == 0) {
        float t = part[0][c];
#pragma unroll
        for (int i = 1; i < 8; i++) t += part[i][c];
        g_vmean[b * DD + d0 + c] = t * (1.0f / SS);
    }
}

// ============================ kernel 4: P @ V ============================
__global__ __launch_bounds__(256, 2) void pv_k(const int* __restrict__ ev, float* __restrict__ out)
{
    int b = blockIdx.z;
    int L = ev[b];
    int q0 = blockIdx.x * BM;
    int d0 = blockIdx.y * BN;

    if (q0 >= L) {   // uniform attention -> vmean broadcast
        const float* vm = g_vmean + b * DD + d0;
        for (int idx = threadIdx.x; idx < BM * (BN / 4); idx += 256) {
            int r = idx >> 5, c4 = (idx & 31) * 4;
            float4 v = *(const float4*)(vm + c4);
            *(float4*)(out + ((size_t)(b * SS + q0 + r)) * DD + d0 + c4) = v;
        }
        return;
    }

    extern __shared__ __align__(128) uint32_t dsm[];
    uint32_t smaddr = smem_u32(dsm);

    int pad = (L + 31) & ~31;
    if (pad > SS) pad = SS;
    int nchunks = pad / BK;

    float acc[2][8][4] = {};
    size_t poff = ((size_t)b * SS + q0) * SS;
    size_t voff = ((size_t)b * DD + d0) * SS;
    pv_mainloop(g_pf + poff, SS, g_vtf + voff, SS, nchunks, smaddr, acc);

    int tid = threadIdx.x, lane = tid & 31, wid = tid >> 5;
    int gid = lane >> 2, tig = lane & 3;
    int row0 = q0 + (wid & 3) * 32 + gid;
    int col0 = d0 + (wid >> 2) * 64 + tig * 2;
    const float* vm = g_vmean + b * DD;
#pragma unroll
    for (int mf = 0; mf < 2; mf++)
#pragma unroll
    for (int h = 0; h < 2; h++) {
        int q = row0 + mf * 16 + h * 8;
        bool qok = q < L;
#pragma unroll
        for (int nf = 0; nf < 8; nf++) {
            int col = col0 + nf * 8;
            float2 v;
            if (qok) { v.x = acc[mf][nf][h*2+0]; v.y = acc[mf][nf][h*2+1]; }
            else     { v.x = vm[col];            v.y = vm[col+1]; }
            *(float2*)(out + (size_t)(b * SS + q) * DD + col) = v;
        }
    }
}

// ============================ launch (fork-join: q/k chain || V chain) ============================
extern "C" void kernel_launch(void* const* d_in, const int* in_sizes, int n_in,
                              void* d_out, int out_size)
{
    const float* x  = (const float*)d_in[0];
    const int*   ev = (const int*)  d_in[1];
    const float* Wq = (const float*)d_in[2];
    const float* bq = (const float*)d_in[3];
    const float* Wk = (const float*)d_in[4];
    const float* bk = (const float*)d_in[5];
    const float* Wv = (const float*)d_in[6];
    const float* bv = (const float*)d_in[7];
    float* out = (float*)d_out;

    cudaFuncSetAttribute(qkv_k,    cudaFuncAttributeMaxDynamicSharedMemorySize, PV_SMEM);
    cudaFuncSetAttribute(scores_k, cudaFuncAttributeMaxDynamicSharedMemorySize, PV_SMEM);
    cudaFuncSetAttribute(pv_k,     cudaFuncAttributeMaxDynamicSharedMemorySize, PV_SMEM);

    int tot4 = NX4 + 3 * NW4;
    split_k<<<(tot4 + 255) / 256, 256>>>((const float4*)x, (const float4*)Wq,
                                         (const float4*)Wk, (const float4*)Wv);

    // fork: V chain on side stream
    cudaEventRecord(g_sp.e_fork, 0);
    cudaStreamWaitEvent(g_sp.s1, g_sp.e_fork, 0);

    // main stream: q/k chain
    qkv_k   <<<dim3((BB*SS)/BM, DD/BN, 2), 256, PV_SMEM>>>(ev, 0, bq, bk, bv);
    scores_k<<<dim3(SS/BM, SS/BN, BB), 256, PV_SMEM>>>(ev);
    softmax_k<<<dim3(SS/8, BB), 256>>>(ev);

    // side stream: V chain
    qkv_k   <<<dim3((BB*SS)/BM, DD/BN, 1), 256, PV_SMEM, g_sp.s1>>>(ev, 2, bq, bk, bv);
    vtrans_k<<<dim3(SS/32, DD/32, BB), dim3(32, 8), 0, g_sp.s1>>>(ev);
    vmean_k <<<dim3(BB, DD/32), 256, 0, g_sp.s1>>>();
    cudaEventRecord(g_sp.e_join, g_sp.s1);

    // join, then pv
    cudaStreamWaitEvent(0, g_sp.e_join, 0);
    pv_k    <<<dim3(SS/BM, DD/BN, BB), 256, PV_SMEM>>>(ev, out);
}

// round 17
// speedup vs baseline: 1.0111x; 1.0111x over previous
#include <cuda_runtime.h>
#include <cuda_fp16.h>
#include <cstdint>

#define BB 8
#define SS 2048
#define DD 512
#define SCALEV 0.04419417382415922f   // 1/sqrt(512)

#define BM 128
#define BN 128
#define BK 32

// ---- single-term fp16 GEMM: 2 tiles, 4 stages, prefetch 3, SW64 ----
#define PV_TBYTES 8192
#define PV_STAGE (2*PV_TBYTES)          // 16384
#define PV_NSTAGE 4
#define PV_SMEM (PV_NSTAGE*PV_STAGE)    // 65536

// ---- scratch (device globals zero-init; never-written rows stay 0) ----
__device__ __half g_xf[BB*SS*DD];
__device__ __half g_wf[3*DD*DD];
__device__ __half g_qf[BB*SS*DD], g_kf[BB*SS*DD];
__device__ float g_v[BB*SS*DD];
__device__ __half g_vtf[BB*DD*SS];
__device__ float g_vmean[BB*DD];
__device__ float g_p[(size_t)BB*SS*SS];
__device__ __half g_pf[(size_t)BB*SS*SS];

// ---- side stream + events (host objects; static init, reused every call) ----
struct StreamPack {
    cudaStream_t s1;
    cudaEvent_t e_fork, e_join;
    StreamPack() {
        cudaStreamCreateWithFlags(&s1, cudaStreamNonBlocking);
        cudaEventCreateWithFlags(&e_fork, cudaEventDisableTiming);
        cudaEventCreateWithFlags(&e_join, cudaEventDisableTiming);
    }
};
static StreamPack g_sp;

// ============================ helpers ============================
__device__ __forceinline__ uint32_t smem_u32(const void* p) {
    uint32_t a;
    asm("{ .reg .u64 t; cvta.to.shared.u64 t, %1; cvt.u32.u64 %0, t; }" : "=r"(a) : "l"(p));
    return a;
}
__device__ __forceinline__ void cp16(uint32_t dst, const void* src) {
    asm volatile("cp.async.cg.shared.global [%0], [%1], 16;" :: "r"(dst), "l"(src));
}
#define CP_COMMIT() asm volatile("cp.async.commit_group;" ::: "memory")
#define CP_WAIT2()  asm volatile("cp.async.wait_group 2;" ::: "memory")
#define CP_WAIT0()  asm volatile("cp.async.wait_group 0;" ::: "memory")

__device__ __forceinline__ void mma_f16(float* c, const uint32_t* a, uint32_t b0, uint32_t b1) {
    asm volatile(
        "mma.sync.aligned.m16n8k16.row.col.f32.f16.f16.f32 "
        "{%0,%1,%2,%3},{%4,%5,%6,%7},{%8,%9},{%0,%1,%2,%3};"
        : "+f"(c[0]), "+f"(c[1]), "+f"(c[2]), "+f"(c[3])
        : "r"(a[0]), "r"(a[1]), "r"(a[2]), "r"(a[3]), "r"(b0), "r"(b1));
}

__device__ __forceinline__ void ldm_x4(uint32_t* r, uint32_t addr) {
    asm volatile("ldmatrix.sync.aligned.m8n8.x4.shared.b16 {%0,%1,%2,%3}, [%4];"
        : "=r"(r[0]), "=r"(r[1]), "=r"(r[2]), "=r"(r[3]) : "r"(addr));
}

// ============================ single-term fp16 mainloop ============================
__device__ __forceinline__ void pv_load_chunk(
    const __half* __restrict__ P, size_t ldp,
    const __half* __restrict__ Vt, size_t ldv,
    int c, int s, uint32_t smaddr, int tid)
{
    uint32_t base = smaddr + s * PV_STAGE;
    const __half* p = P + (size_t)c * BK;
    const __half* v = Vt + (size_t)c * BK;
#pragma unroll
    for (int i = 0; i < 2; i++) {
        int idx = tid + i * 256;
        int r = idx >> 2, cb = (idx & 3) * 16;
        uint32_t doff = (uint32_t)r * 64 + (cb ^ ((r & 6) << 3));
        cp16(base + doff,             p + (size_t)r * ldp + (cb >> 1));
        cp16(base + PV_TBYTES + doff, v + (size_t)r * ldv + (cb >> 1));
    }
}

__device__ __forceinline__ void pv_mainloop(
    const __half* __restrict__ P, size_t ldp,
    const __half* __restrict__ Vt, size_t ldv,
    int nchunks, uint32_t smaddr,
    float acc[2][8][4])
{
    const int tid = threadIdx.x;
    const int lane = tid & 31, wid = tid >> 5;
    const int q = lane >> 3, r = lane & 7;
    const int m_base = (wid & 3) * 32;
    const int n_base = (wid >> 2) * 64;

    const int arow = m_base + (q & 1) * 8 + r;
    const int brow = n_base + (q >> 1) * 8 + r;
    const uint32_t aoff0 = (uint32_t)arow * 64 + ((arow & 6) << 3);
    const uint32_t boff0 = (uint32_t)brow * 64 + ((brow & 6) << 3);
    const uint32_t acol = (uint32_t)(q >> 1) * 16;
    const uint32_t bcol = (uint32_t)(q & 1) * 16;

#pragma unroll
    for (int i = 0; i < 3; i++) {
        if (i < nchunks) pv_load_chunk(P, ldp, Vt, ldv, i, i, smaddr, tid);
        CP_COMMIT();
    }

    int s = 0;
    for (int c = 0; c < nchunks; c++) {
        CP_WAIT2();
        __syncthreads();
        int s3 = s + 3 >= PV_NSTAGE ? s + 3 - PV_NSTAGE : s + 3;
        if (c + 3 < nchunks)
            pv_load_chunk(P, ldp, Vt, ldv, c + 3, s3, smaddr, tid);
        CP_COMMIT();

        uint32_t sbase = smaddr + s * PV_STAGE;
#pragma unroll
        for (int ks = 0; ks < 2; ks++) {
            uint32_t axo = aoff0 ^ (acol + ks * 32);
            uint32_t bxo = boff0 ^ (bcol + ks * 32);
            uint32_t ah[2][4];
            ldm_x4(ah[0], sbase + axo);
            ldm_x4(ah[1], sbase + 1024 + axo);
#pragma unroll
            for (int p = 0; p < 4; p++) {
                uint32_t bh[4];
                ldm_x4(bh, sbase + PV_TBYTES + p*1024 + bxo);
                mma_f16(acc[0][2*p],   ah[0], bh[0], bh[1]);
                mma_f16(acc[1][2*p],   ah[1], bh[0], bh[1]);
                mma_f16(acc[0][2*p+1], ah[0], bh[2], bh[3]);
                mma_f16(acc[1][2*p+1], ah[1], bh[2], bh[3]);
            }
        }
        s = (s + 1 == PV_NSTAGE) ? 0 : s + 1;
    }
    CP_WAIT0();
}

// ============================ split inputs: all -> single fp16 ============================
#define NX4 (BB*SS*DD/4)
#define NW4 (DD*DD/4)
__global__ __launch_bounds__(256) void split_k(
    const float4* __restrict__ x, const float4* __restrict__ Wq,
    const float4* __restrict__ Wk, const float4* __restrict__ Wv)
{
    int i = blockIdx.x * 256 + threadIdx.x;
    const float4* in; __half2* o2; int j;
    if (i < NX4) {
        in = x; j = i; o2 = (__half2*)g_xf;
    } else {
        int t = i - NX4;
        int w = t / NW4; j = t - w * NW4;
        in = (w == 0) ? Wq : (w == 1) ? Wk : Wv;
        o2 = (__half2*)(g_wf + (size_t)w * DD * DD);
    }
    float4 v = in[j];
    o2[j*2]   = __halves2half2(__float2half_rn(v.x), __float2half_rn(v.y));
    o2[j*2+1] = __halves2half2(__float2half_rn(v.z), __float2half_rn(v.w));
}

// ============================ kernel 1: QKV (zbase selects q/k vs v) ============================
__global__ __launch_bounds__(256, 2) void qkv_k(
    const int* __restrict__ ev, int zbase,
    const float* __restrict__ bq, const float* __restrict__ bk, const float* __restrict__ bv)
{
    int m0 = blockIdx.x * BM;
    int z = zbase + blockIdx.z;
    if (z < 2) {                        // q/k rows >= L never read downstream
        int b = m0 >> 11;
        if ((m0 & (SS - 1)) >= ev[b]) return;
    }

    extern __shared__ __align__(128) uint32_t dsm[];
    uint32_t smaddr = smem_u32(dsm);

    int e0 = blockIdx.y * BN;
    const float* bias = (z == 0) ? bq : (z == 1) ? bk : bv;

    float acc[2][8][4] = {};
    pv_mainloop(g_xf + (size_t)m0 * DD, DD,
                g_wf + (size_t)z * DD * DD + (size_t)e0 * DD, DD,
                DD / BK, smaddr, acc);

    int tid = threadIdx.x, lane = tid & 31, wid = tid >> 5;
    int gid = lane >> 2, tig = lane & 3;
    int row0 = m0 + (wid & 3) * 32 + gid;
    int col0 = e0 + (wid >> 2) * 64 + tig * 2;
#pragma unroll
    for (int mf = 0; mf < 2; mf++)
#pragma unroll
    for (int h = 0; h < 2; h++) {
        int row = row0 + mf * 16 + h * 8;
#pragma unroll
        for (int nf = 0; nf < 8; nf++) {
            int col = col0 + nf * 8;
            float y0 = acc[mf][nf][h*2+0] + bias[col];
            float y1 = acc[mf][nf][h*2+1] + bias[col+1];
            size_t off = (size_t)row * DD + col;
            if (z == 2) {
                *(float2*)(g_v + off) = make_float2(y0, y1);
            } else {
                __half* o = (z == 0) ? g_qf : g_kf;
                *(__half2*)(o + off) = __halves2half2(__float2half_rn(y0), __float2half_rn(y1));
            }
        }
    }
}

// ============================ kernel 2: scores ============================
__global__ __launch_bounds__(256, 2) void scores_k(const int* __restrict__ ev)
{
    int b = blockIdx.z;
    int L = ev[b];
    int q0 = blockIdx.x * BM;
    int k0 = blockIdx.y * BN;
    if (q0 >= L || k0 >= L) return;

    extern __shared__ __align__(128) uint32_t dsm[];
    uint32_t smaddr = smem_u32(dsm);

    float acc[2][8][4] = {};
    size_t qoff = ((size_t)b * SS + q0) * DD;
    size_t koff = ((size_t)b * SS + k0) * DD;
    pv_mainloop(g_qf + qoff, DD, g_kf + koff, DD, DD / BK, smaddr, acc);

    float* P = g_p + (size_t)b * SS * SS;
    int tid = threadIdx.x, lane = tid & 31, wid = tid >> 5;
    int gid = lane >> 2, tig = lane & 3;
    int row0 = q0 + (wid & 3) * 32 + gid;
    int col0 = k0 + (wid >> 2) * 64 + tig * 2;
#pragma unroll
    for (int mf = 0; mf < 2; mf++)
#pragma unroll
    for (int h = 0; h < 2; h++) {
        int q = row0 + mf * 16 + h * 8;
        if (q >= L) continue;
#pragma unroll
        for (int nf = 0; nf < 8; nf++) {
            int k = col0 + nf * 8;
            if (k + 1 < L) {
                float2 v;
                v.x = acc[mf][nf][h*2+0] * SCALEV;
                v.y = acc[mf][nf][h*2+1] * SCALEV;
                *(float2*)(P + (size_t)q * SS + k) = v;
            } else if (k < L) {
                P[(size_t)q * SS + k] = acc[mf][nf][h*2+0] * SCALEV;
            }
        }
    }
}

// ============================ kernel 3: softmax (2 warps/row, float4) ============================
__global__ __launch_bounds__(256) void softmax_k(const int* __restrict__ ev)
{
    int b = blockIdx.y;
    int L = ev[b];
    int row_base = blockIdx.x * 4;
    if (row_base >= L) return;          // uniform whole-block exit (before any barrier)

    int wid = threadIdx.x >> 5, lane = threadIdx.x & 31;
    int rrow = wid >> 1, half = wid & 1;
    int q = row_base + rrow;
    bool alive = q < L;                 // dead rows: g_p row is never-written (zero) -> finite

    size_t off = ((size_t)b * SS + q) * SS;
    const float4* row4 = (const float4*)(g_p + off);

    float4 v[8];
    float m = -3.4e38f;
#pragma unroll
    for (int i = 0; i < 8; i++) {
        int k = half * 1024 + lane * 4 + i * 128;
        float4 t = row4[half * 256 + lane + i * 32];
        t.x = (k + 0 < L) ? t.x : -3.4e38f;
        t.y = (k + 1 < L) ? t.y : -3.4e38f;
        t.z = (k + 2 < L) ? t.z : -3.4e38f;
        t.w = (k + 3 < L) ? t.w : -3.4e38f;
        v[i] = t;
        m = fmaxf(m, fmaxf(fmaxf(t.x, t.y), fmaxf(t.z, t.w)));
    }
#pragma unroll
    for (int o = 16; o > 0; o >>= 1) m = fmaxf(m, __shfl_xor_sync(0xffffffffu, m, o));

    __shared__ float red[2][8];
    if (lane == 0) red[0][wid] = m;
    __syncthreads();
    m = fmaxf(red[0][wid & 6], red[0][(wid & 6) | 1]);

    float s = 0.f;
#pragma unroll
    for (int i = 0; i < 8; i++) {
        v[i].x = __expf(v[i].x - m);
        v[i].y = __expf(v[i].y - m);
        v[i].z = __expf(v[i].z - m);
        v[i].w = __expf(v[i].w - m);
        s += (v[i].x + v[i].y) + (v[i].z + v[i].w);
    }
#pragma unroll
    for (int o = 16; o > 0; o >>= 1) s += __shfl_xor_sync(0xffffffffu, s, o);
    if (lane == 0) red[1][wid] = s;
    __syncthreads();
    s = red[1][wid & 6] + red[1][(wid & 6) | 1];
    float inv = 1.0f / s;

    int pad = (L + 31) & ~31;
    if (pad > SS) pad = SS;
    __half2* out2 = (__half2*)(g_pf + off);
    if (alive) {
#pragma unroll
        for (int i = 0; i < 8; i++) {
            int k = half * 1024 + lane * 4 + i * 128;
            if (k < pad) {
                out2[(k >> 1)]     = __halves2half2(__float2half_rn(v[i].x * inv),
                                                    __float2half_rn(v[i].y * inv));
                out2[(k >> 1) + 1] = __halves2half2(__float2half_rn(v[i].z * inv),
                                                    __float2half_rn(v[i].w * inv));
            }
        }
    }
}

// ============================ transpose V -> vT (fp16; dead columns skipped) ============================
__global__ void vtrans_k(const int* __restrict__ ev)
{
    __shared__ float t[32][33];
    int b = blockIdx.z;
    int s0 = blockIdx.x * 32;
    int pad = (ev[b] + 31) & ~31;
    if (s0 >= pad) return;
    int d0 = blockIdx.y * 32;
    int tx = threadIdx.x, ty = threadIdx.y;
    const float* v = g_v + (size_t)b * SS * DD;
#pragma unroll
    for (int i = 0; i < 4; i++)
        t[ty + i*8][tx] = v[(size_t)(s0 + ty + i*8) * DD + d0 + tx];
    __syncthreads();
#pragma unroll
    for (int i = 0; i < 4; i++) {
        size_t o = (size_t)b * DD * SS + (size_t)(d0 + ty + i*8) * SS + s0 + tx;
        g_vtf[o] = __float2half_rn(t[tx][ty + i*8]);
    }
}

// ============================ vmean (coalesced, deterministic) ============================
__global__ __launch_bounds__(256) void vmean_k()
{
    __shared__ float part[8][32];
    int b = blockIdx.x;
    int d0 = blockIdx.y * 32;
    int tid = threadIdx.x;
    int c = tid & 31, h = tid >> 5;

    const float* v = g_v + (size_t)b * SS * DD + d0 + c;
    float s = 0.f;
    for (int r = h; r < SS; r += 8)
        s += v[(size_t)r * DD];
    part[h][c] = s;
    __syncthreads();

    if (h == 0) {
        float t = part[0][c];
#pragma unroll
        for (int i = 1; i < 8; i++) t += part[i][c];
        g_vmean[b * DD + d0 + c] = t * (1.0f / SS);
    }
}

// ============================ kernel 4a: dead q-tiles (vmean broadcast; V-chain only) ============================
__global__ __launch_bounds__(256) void pv_dead_k(const int* __restrict__ ev, float* __restrict__ out)
{
    int b = blockIdx.z;
    int L = ev[b];
    int q0 = blockIdx.x * BM;
    if (q0 < L) return;
    int d0 = blockIdx.y * BN;
    const float* vm = g_vmean + b * DD + d0;
    for (int idx = threadIdx.x; idx < BM * (BN / 4); idx += 256) {
        int r = idx >> 5, c4 = (idx & 31) * 4;
        float4 v = *(const float4*)(vm + c4);
        *(float4*)(out + ((size_t)(b * SS + q0 + r)) * DD + d0 + c4) = v;
    }
}

// ============================ kernel 4b: P @ V (live tiles) ============================
__global__ __launch_bounds__(256, 2) void pv_k(const int* __restrict__ ev, float* __restrict__ out)
{
    int b = blockIdx.z;
    int L = ev[b];
    int q0 = blockIdx.x * BM;
    int d0 = blockIdx.y * BN;
    if (q0 >= L) return;                // handled by pv_dead_k

    extern __shared__ __align__(128) uint32_t dsm[];
    uint32_t smaddr = smem_u32(dsm);

    int pad = (L + 31) & ~31;
    if (pad > SS) pad = SS;
    int nchunks = pad / BK;

    float acc[2][8][4] = {};
    size_t poff = ((size_t)b * SS + q0) * SS;
    size_t voff = ((size_t)b * DD + d0) * SS;
    pv_mainloop(g_pf + poff, SS, g_vtf + voff, SS, nchunks, smaddr, acc);

    int tid = threadIdx.x, lane = tid & 31, wid = tid >> 5;
    int gid = lane >> 2, tig = lane & 3;
    int row0 = q0 + (wid & 3) * 32 + gid;
    int col0 = d0 + (wid >> 2) * 64 + tig * 2;
    const float* vm = g_vmean + b * DD;
#pragma unroll
    for (int mf = 0; mf < 2; mf++)
#pragma unroll
    for (int h = 0; h < 2; h++) {
        int q = row0 + mf * 16 + h * 8;
        bool qok = q < L;
#pragma unroll
        for (int nf = 0; nf < 8; nf++) {
            int col = col0 + nf * 8;
            float2 v;
            if (qok) { v.x = acc[mf][nf][h*2+0]; v.y = acc[mf][nf][h*2+1]; }
            else     { v.x = vm[col];            v.y = vm[col+1]; }
            *(float2*)(out + (size_t)(b * SS + q) * DD + col) = v;
        }
    }
}

// ============================ launch (fork-join: q/k chain || V chain) ============================
extern "C" void kernel_launch(void* const* d_in, const int* in_sizes, int n_in,
                              void* d_out, int out_size)
{
    const float* x  = (const float*)d_in[0];
    const int*   ev = (const int*)  d_in[1];
    const float* Wq = (const float*)d_in[2];
    const float* bq = (const float*)d_in[3];
    const float* Wk = (const float*)d_in[4];
    const float* bk = (const float*)d_in[5];
    const float* Wv = (const float*)d_in[6];
    const float* bv = (const float*)d_in[7];
    float* out = (float*)d_out;

    cudaFuncSetAttribute(qkv_k,    cudaFuncAttributeMaxDynamicSharedMemorySize, PV_SMEM);
    cudaFuncSetAttribute(scores_k, cudaFuncAttributeMaxDynamicSharedMemorySize, PV_SMEM);
    cudaFuncSetAttribute(pv_k,     cudaFuncAttributeMaxDynamicSharedMemorySize, PV_SMEM);

    int tot4 = NX4 + 3 * NW4;
    split_k<<<(tot4 + 255) / 256, 256>>>((const float4*)x, (const float4*)Wq,
                                         (const float4*)Wk, (const float4*)Wv);

    // fork: V chain on side stream
    cudaEventRecord(g_sp.e_fork, 0);
    cudaStreamWaitEvent(g_sp.s1, g_sp.e_fork, 0);

    // main stream: q/k chain
    qkv_k   <<<dim3((BB*SS)/BM, DD/BN, 2), 256, PV_SMEM>>>(ev, 0, bq, bk, bv);
    scores_k<<<dim3(SS/BM, SS/BN, BB), 256, PV_SMEM>>>(ev);
    softmax_k<<<dim3(SS/4, BB), 256>>>(ev);

    // side stream: V chain, then dead-tile output broadcast (needs only vmean)
    qkv_k   <<<dim3((BB*SS)/BM, DD/BN, 1), 256, PV_SMEM, g_sp.s1>>>(ev, 2, bq, bk, bv);
    vtrans_k<<<dim3(SS/32, DD/32, BB), dim3(32, 8), 0, g_sp.s1>>>(ev);
    vmean_k <<<dim3(BB, DD/32), 256, 0, g_sp.s1>>>();
    pv_dead_k<<<dim3(SS/BM, DD/BN, BB), 256, 0, g_sp.s1>>>(ev, out);
    cudaEventRecord(g_sp.e_join, g_sp.s1);   // join AFTER all s1 work (capture requires full rejoin)

    // join, then live pv
    cudaStreamWaitEvent(0, g_sp.e_join, 0);
    pv_k    <<<dim3(SS/BM, DD/BN, BB), 256, PV_SMEM>>>(ev, out);
}